// round 1
// baseline (speedup 1.0000x reference)
#include <cuda_runtime.h>
#include <math.h>

// Problem constants (fixed by the dataset)
#define BATCH   2
#define SQ      2048
#define SKV     2048
#define DIM     1024
#define HEADS   16
#define DHEAD   64
#define INNER   1024            // HEADS * DHEAD
#define MQ      (BATCH * SQ)    // 4096 rows for Q-side GEMMs
#define MKV     (BATCH * SKV)   // 4096 rows for KV-side GEMM

// Scratch (no cudaMalloc allowed): Q [4096,1024], KV [4096,2048] (K|V), O [4096,1024]
__device__ float g_q [MQ  * INNER];
__device__ float g_kv[MKV * 2 * INNER];
__device__ float g_o [MQ  * INNER];

// ---------------------------------------------------------------------------
// Classic 128x128x8 SGEMM, 256 threads, 8x8 per thread. Row-major A[M,K],
// B[K,N] (with ldb), C[M,N] (with ldc). Optional bias added per column.
// All dims here are multiples of 128/8 so no bounds checks.
// ---------------------------------------------------------------------------
__global__ __launch_bounds__(256) void sgemm128(
    const float* __restrict__ A, const float* __restrict__ Bm,
    float* __restrict__ C, const float* __restrict__ bias,
    int K, int lda, int ldb, int ldc)
{
    __shared__ float As[8][128];
    __shared__ float Bs[8][128];

    const int tid  = threadIdx.x;
    const int brow = blockIdx.y * 128;
    const int bcol = blockIdx.x * 128;

    const int arow   = tid >> 1;          // 0..127
    const int acol   = (tid & 1) * 4;     // 0 or 4
    const int browb  = tid >> 5;          // 0..7
    const int bcolb  = (tid & 31) * 4;    // 0..124

    const int ty = tid >> 4;              // 0..15
    const int tx = tid & 15;              // 0..15

    float acc[8][8];
    #pragma unroll
    for (int i = 0; i < 8; i++)
        #pragma unroll
        for (int j = 0; j < 8; j++) acc[i][j] = 0.f;

    const float* Aptr = A  + (size_t)(brow + arow) * lda + acol;
    const float* Bptr = Bm + (size_t)browb * ldb + bcol + bcolb;

    for (int k0 = 0; k0 < K; k0 += 8) {
        float4 av = *(const float4*)(Aptr + k0);
        float4 bv = *(const float4*)(Bptr + (size_t)k0 * ldb);

        As[acol + 0][arow] = av.x;
        As[acol + 1][arow] = av.y;
        As[acol + 2][arow] = av.z;
        As[acol + 3][arow] = av.w;
        *(float4*)&Bs[browb][bcolb] = bv;
        __syncthreads();

        #pragma unroll
        for (int k = 0; k < 8; k++) {
            float a[8], b[8];
            #pragma unroll
            for (int i = 0; i < 8; i++) a[i] = As[k][ty * 8 + i];
            #pragma unroll
            for (int j = 0; j < 8; j++) b[j] = Bs[k][tx * 8 + j];
            #pragma unroll
            for (int i = 0; i < 8; i++)
                #pragma unroll
                for (int j = 0; j < 8; j++)
                    acc[i][j] += a[i] * b[j];
        }
        __syncthreads();
    }

    #pragma unroll
    for (int i = 0; i < 8; i++) {
        const int r = brow + ty * 8 + i;
        float* crow = C + (size_t)r * ldc + bcol + tx * 8;
        #pragma unroll
        for (int j = 0; j < 8; j += 4) {
            float4 v;
            v.x = acc[i][j + 0]; v.y = acc[i][j + 1];
            v.z = acc[i][j + 2]; v.w = acc[i][j + 3];
            if (bias) {
                const int c0 = bcol + tx * 8 + j;
                v.x += bias[c0 + 0]; v.y += bias[c0 + 1];
                v.z += bias[c0 + 2]; v.w += bias[c0 + 3];
            }
            *(float4*)(crow + j) = v;
        }
    }
}

// ---------------------------------------------------------------------------
// Flash-style attention, fp32. One block = (b, h, 64-query tile); 64 threads,
// one thread per query row. KV streamed through smem in 32-row tiles.
// Q layout: [B*SQ, INNER] (head h at cols h*64..). KV layout: [B*SKV, 2*INNER]
// (K at cols h*64, V at cols INNER + h*64).
// ---------------------------------------------------------------------------
__global__ __launch_bounds__(64) void attn_kernel(
    const float* __restrict__ Q, const float* __restrict__ KV,
    float* __restrict__ O)
{
    const int qt = blockIdx.x;   // 0..31
    const int h  = blockIdx.y;   // 0..15
    const int b  = blockIdx.z;   // 0..1
    const int t  = threadIdx.x;  // 0..63

    __shared__ float Ks[32][64];
    __shared__ float Vs[32][64];

    const float scale = 0.125f;  // 64^-0.5

    // Load this thread's query row into registers
    float q[64];
    {
        const float* qrow = Q + ((size_t)b * SQ + qt * 64 + t) * INNER + h * DHEAD;
        #pragma unroll
        for (int d = 0; d < 64; d += 4) {
            float4 v = *(const float4*)(qrow + d);
            q[d + 0] = v.x; q[d + 1] = v.y; q[d + 2] = v.z; q[d + 3] = v.w;
        }
    }

    float m = -INFINITY, l = 0.f;
    float o[64];
    #pragma unroll
    for (int d = 0; d < 64; d++) o[d] = 0.f;

    for (int kv0 = 0; kv0 < SKV; kv0 += 32) {
        __syncthreads();
        // cooperative tile load: 32 rows x 16 float4 for K and V each
        for (int i = t; i < 32 * 16; i += 64) {
            const int j  = i >> 4;
            const int d4 = i & 15;
            const size_t base = ((size_t)b * SKV + kv0 + j) * (2 * INNER) + h * DHEAD;
            ((float4*)Ks[j])[d4] = *(const float4*)(KV + base + d4 * 4);
            ((float4*)Vs[j])[d4] = *(const float4*)(KV + base + INNER + d4 * 4);
        }
        __syncthreads();

        // scores for this tile
        float s[32];
        float tmax = -INFINITY;
        #pragma unroll
        for (int j = 0; j < 32; j++) {
            float acc = 0.f;
            #pragma unroll
            for (int d = 0; d < 64; d++) acc += q[d] * Ks[j][d];
            s[j] = acc * scale;
            tmax = fmaxf(tmax, s[j]);
        }

        // online softmax rescale (once per tile)
        const float mnew = fmaxf(m, tmax);
        const float c = __expf(m - mnew);   // 0 on first tile (m = -inf)
        l *= c;
        #pragma unroll
        for (int d = 0; d < 64; d++) o[d] *= c;
        m = mnew;

        #pragma unroll
        for (int j = 0; j < 32; j++) {
            const float p = __expf(s[j] - m);
            l += p;
            #pragma unroll
            for (int d = 0; d < 64; d++) o[d] += p * Vs[j][d];
        }
    }

    const float inv = 1.f / l;
    float* orow = O + ((size_t)b * SQ + qt * 64 + t) * INNER + h * DHEAD;
    #pragma unroll
    for (int d = 0; d < 64; d += 4) {
        float4 v;
        v.x = o[d + 0] * inv; v.y = o[d + 1] * inv;
        v.z = o[d + 2] * inv; v.w = o[d + 3] * inv;
        *(float4*)(orow + d) = v;
    }
}

// ---------------------------------------------------------------------------
// kernel_launch: x_q, x_kv, W_qkv, W_out, b_out  ->  out [B, SQ, DIM] fp32
// ---------------------------------------------------------------------------
extern "C" void kernel_launch(void* const* d_in, const int* in_sizes, int n_in,
                              void* d_out, int out_size)
{
    const float* x_q   = (const float*)d_in[0];
    const float* x_kv  = (const float*)d_in[1];
    const float* W_qkv = (const float*)d_in[2];  // [1024, 3072]
    const float* W_out = (const float*)d_in[3];  // [1024, 1024]
    const float* b_out = (const float*)d_in[4];  // [1024]
    float* out = (float*)d_out;

    float *q, *kv, *o;
    cudaGetSymbolAddress((void**)&q,  g_q);
    cudaGetSymbolAddress((void**)&kv, g_kv);
    cudaGetSymbolAddress((void**)&o,  g_o);

    // Q = x_q @ W_qkv[:, 0:1024]            -> [4096, 1024]
    sgemm128<<<dim3(INNER / 128, MQ / 128), 256>>>(
        x_q, W_qkv, q, nullptr, DIM, DIM, 3 * INNER, INNER);

    // KV = x_kv @ W_qkv[:, 1024:3072]       -> [4096, 2048]  (K | V)
    sgemm128<<<dim3(2 * INNER / 128, MKV / 128), 256>>>(
        x_kv, W_qkv + INNER, kv, nullptr, DIM, DIM, 3 * INNER, 2 * INNER);

    // attention                              -> O [4096, 1024]
    attn_kernel<<<dim3(SQ / 64, HEADS, BATCH), 64>>>(q, kv, o);

    // out = O @ W_out + b_out                -> [4096, 1024]
    sgemm128<<<dim3(DIM / 128, MQ / 128), 256>>>(
        o, W_out, out, b_out, INNER, INNER, DIM, DIM);
}